// round 15
// baseline (speedup 1.0000x reference)
#include <cuda_runtime.h>
#include <math.h>

#define NN 50000
#define EE 600000
#define DD 128
#define CC 8
#define SCALEF 0.08838834764831845f   // 128^-0.5
#define NBLK 196                       // scan blocks: ceil(50000/256)
#define QPTILES 782                    // ceil(50000/64)

// ---------------- static device scratch ----------------
__device__ __align__(16) int   g_deg[NN];
__device__ __align__(16) int   g_rowptr[NN + 1];
__device__ __align__(16) int   g_cursor[NN];
__device__ __align__(16) int   g_eids[EE];
__device__ __align__(16) int   g_bsum[NBLK];
__device__ __align__(16) float g_WkT[DD * DD];
__device__ __align__(16) float g_Wqk[DD * DD];
__device__ __align__(16) float g_Wvo[DD * DD];
__device__ __align__(16) float g_bqk[DD];
__device__ __align__(16) float g_bvo[DD];
__device__ __align__(16) float g_wqbk[DD];
__device__            float g_bqbk;
__device__ __align__(16) float g_qp[(size_t)NN * DD];
__device__ __align__(16) float g_qb[NN];
__device__ __align__(16) float g_ex[EE];     // exp(attn), EDGE order
__device__ __align__(16) int   g_as[EE];     // cluster assign, EDGE order
__device__ __align__(16) int   g_cflag[CC];
__device__ __align__(16) float g_U[(size_t)NN * DD];
__device__ __align__(16) float g_S[NN];

// ---------------- packed f32x2 helpers ----------------
__device__ __forceinline__ unsigned long long pack2(float x) {
    unsigned long long r;
    unsigned u = __float_as_uint(x);
    asm("mov.b64 %0, {%1, %1};" : "=l"(r) : "r"(u));
    return r;
}
__device__ __forceinline__ void ffma2(unsigned long long& d, unsigned long long a,
                                      unsigned long long b) {
    asm("fma.rn.f32x2 %0, %1, %2, %0;" : "+l"(d) : "l"(a), "l"(b));
}
__device__ __forceinline__ void unpack2(unsigned long long v, float& lo, float& hi) {
    unsigned a, b;
    asm("mov.b64 {%0, %1}, %2;" : "=r"(a), "=r"(b) : "l"(v));
    lo = __uint_as_float(a); hi = __uint_as_float(b);
}
__device__ __forceinline__ float dot4(float4 a, float4 b) {
    return a.x * b.x + a.y * b.y + a.z * b.z + a.w * b.w;
}

// ---------------- prep + init fused ----------------
__global__ void k_prep(const float* __restrict__ Wq, const float* __restrict__ bq,
                       const float* __restrict__ Wk, const float* __restrict__ bk,
                       const float* __restrict__ bv, const float* __restrict__ Wo) {
    int b = blockIdx.x;
    if (b < DD) {
        int r = b, c = threadIdx.x;
        g_WkT[c * DD + r] = Wk[r * DD + c];
    } else if (b == DD) {
        int j = threadIdx.x;
        float s1 = 0.f, s2 = 0.f, s3 = 0.f;
        for (int l = 0; l < DD; l++) {
            s1 += bq[l] * Wk[j * DD + l];      // bqk  = bq @ Wk^T
            s2 += bv[l] * Wo[l * DD + j];      // bvo  = bv @ Wo
            s3 += Wq[j * DD + l] * bk[l];      // wqbk = Wq @ bk
        }
        g_bqk[j] = s1; g_bvo[j] = s2; g_wqbk[j] = s3;
        if (j < CC) g_cflag[j] = 0;
        if (j == 0) {
            float t = 0.f;
            for (int l = 0; l < DD; l++) t += bq[l] * bk[l];
            g_bqbk = t;
        }
    } else {
        int i = (b - DD - 1) * blockDim.x + threadIdx.x;
        if (i < NN) g_deg[i] = 0;
    }
}

// ---------------- shared GEMM tile helpers (64 rows x 128 cols, 256 thr) ----
__device__ __forceinline__ void dgemm_weight(const float* __restrict__ A,
                                             const float* __restrict__ W,
                                             float* __restrict__ out, int tile) {
    extern __shared__ float smem[];
    float4* Ws4 = (float4*)smem;
    float4* As4 = (float4*)(smem + DD * DD);
    const ulonglong2* WsU = (const ulonglong2*)smem;

    for (int i = threadIdx.x; i < DD * DD / 4; i += 256)
        Ws4[i] = ((const float4*)W)[i];
    int row0 = tile * 64;
    for (int i = threadIdx.x; i < 64 * 32; i += 256) {
        int rr = i >> 5, cc = i & 31;
        As4[i] = ((const float4*)A)[(size_t)(row0 + rr) * 32 + cc];
    }
    __syncthreads();

    int r = threadIdx.x >> 5;
    int jc = threadIdx.x & 31;

    unsigned long long acc2[8][2];
#pragma unroll
    for (int a = 0; a < 8; a++) { acc2[a][0] = 0ull; acc2[a][1] = 0ull; }

#pragma unroll 2
    for (int k4 = 0; k4 < 32; k4++) {
        float4 a4[8];
#pragma unroll
        for (int rr = 0; rr < 8; rr++) a4[rr] = As4[(r * 8 + rr) * 32 + k4];
#pragma unroll
        for (int kk = 0; kk < 4; kk++) {
            int k = k4 * 4 + kk;
            ulonglong2 w = WsU[k * 32 + jc];
#pragma unroll
            for (int rr = 0; rr < 8; rr++) {
                float av = (kk == 0) ? a4[rr].x : (kk == 1) ? a4[rr].y
                         : (kk == 2) ? a4[rr].z : a4[rr].w;
                unsigned long long av2 = pack2(av);
                ffma2(acc2[rr][0], av2, w.x);
                ffma2(acc2[rr][1], av2, w.y);
            }
        }
    }
#pragma unroll
    for (int rr = 0; rr < 8; rr++) {
        int row = row0 + r * 8 + rr;
        float o[4];
        unpack2(acc2[rr][0], o[0], o[1]);
        unpack2(acc2[rr][1], o[2], o[3]);
        ((float4*)out)[(size_t)row * 32 + jc] = make_float4(o[0], o[1], o[2], o[3]);
    }
}

__device__ __forceinline__ void dgemm_qp(const float* __restrict__ A, int tile) {
    extern __shared__ float smem[];
    float4* Ws4 = (float4*)smem;
    float4* As4 = (float4*)(smem + DD * DD);
    const ulonglong2* WsU = (const ulonglong2*)smem;

    for (int i = threadIdx.x; i < DD * DD / 4; i += 256)
        Ws4[i] = ((const float4*)g_Wqk)[i];
    int row0 = tile * 64;
    for (int i = threadIdx.x; i < 64 * 32; i += 256) {
        int rr = i >> 5, cc = i & 31;
        float4 v = make_float4(0.f, 0.f, 0.f, 0.f);
        if (row0 + rr < NN) v = ((const float4*)A)[(size_t)(row0 + rr) * 32 + cc];
        As4[i] = v;
    }
    __syncthreads();

    int r = threadIdx.x >> 5;
    int jc = threadIdx.x & 31;

    unsigned long long acc2[8][2];
#pragma unroll
    for (int a = 0; a < 8; a++) { acc2[a][0] = 0ull; acc2[a][1] = 0ull; }

#pragma unroll 2
    for (int k4 = 0; k4 < 32; k4++) {
        float4 a4[8];
#pragma unroll
        for (int rr = 0; rr < 8; rr++) a4[rr] = As4[(r * 8 + rr) * 32 + k4];
#pragma unroll
        for (int kk = 0; kk < 4; kk++) {
            int k = k4 * 4 + kk;
            ulonglong2 w = WsU[k * 32 + jc];
#pragma unroll
            for (int rr = 0; rr < 8; rr++) {
                float av = (kk == 0) ? a4[rr].x : (kk == 1) ? a4[rr].y
                         : (kk == 2) ? a4[rr].z : a4[rr].w;
                unsigned long long av2 = pack2(av);
                ffma2(acc2[rr][0], av2, w.x);
                ffma2(acc2[rr][1], av2, w.y);
            }
        }
    }

    // fused qb epilogue
    {
        float4 wq = ((const float4*)g_wqbk)[jc];
#pragma unroll
        for (int rr = 0; rr < 8; rr++) {
            int row = row0 + r * 8 + rr;
            float4 a0 = As4[(r * 8 + rr) * 32 + jc];
            float part = dot4(a0, wq);
#pragma unroll
            for (int off = 16; off; off >>= 1)
                part += __shfl_xor_sync(0xffffffffu, part, off);
            if (jc == 0 && row < NN) g_qb[row] = part + g_bqbk;
        }
    }

    float4 b0 = ((const float4*)g_bqk)[jc];
#pragma unroll
    for (int rr = 0; rr < 8; rr++) {
        int row = row0 + r * 8 + rr;
        if (row < NN) {
            float o[4];
            unpack2(acc2[rr][0], o[0], o[1]);
            unpack2(acc2[rr][1], o[2], o[3]);
            o[0] += b0.x; o[1] += b0.y; o[2] += b0.z; o[3] += b0.w;
            ((float4*)g_qp)[(size_t)row * 32 + jc] = make_float4(o[0], o[1], o[2], o[3]);
        }
    }
}

// ---------------- combo1: weight GEMMs + histogram ----------------
__global__ void __launch_bounds__(256, 2)
k_combo1(const float* __restrict__ Wq, const float* __restrict__ Wv,
         const float* __restrict__ Wo, const int* __restrict__ src) {
    if (blockIdx.x < 2) {
        dgemm_weight(Wq, g_WkT, g_Wqk, blockIdx.x);
    } else if (blockIdx.x < 4) {
        dgemm_weight(Wv, Wo, g_Wvo, blockIdx.x - 2);
    } else {
        int i = (blockIdx.x - 4) * 256 + threadIdx.x;
        if (i < EE) atomicAdd(&g_deg[src[i]], 1);
    }
}

// ---------------- combo2: qp GEMM + scanA ----------------
__global__ void __launch_bounds__(256, 2)
k_combo2(const float* __restrict__ nf) {
    if (blockIdx.x < QPTILES) {
        dgemm_qp(nf, blockIdx.x);
    } else {
        __shared__ int red[256];
        int sb = blockIdx.x - QPTILES;
        int i = sb * 256 + threadIdx.x;
        int v = (i < NN) ? g_deg[i] : 0;
        red[threadIdx.x] = v;
        __syncthreads();
        for (int off = 128; off; off >>= 1) {
            if (threadIdx.x < off) red[threadIdx.x] += red[threadIdx.x + off];
            __syncthreads();
        }
        if (threadIdx.x == 0) g_bsum[sb] = red[0];
    }
}

// ---------------- scanC2: per-block offset from bsum + local scan ----------
__global__ void k_scanC2() {
    __shared__ int s[256];
    __shared__ int s2[256];
    int tid = threadIdx.x, bid = blockIdx.x;
    int v = (tid < bid) ? g_bsum[tid] : 0;
    s2[tid] = v;
    __syncthreads();
    for (int off = 128; off; off >>= 1) {
        if (tid < off) s2[tid] += s2[tid + off];
        __syncthreads();
    }
    int base = s2[0];

    int i = bid * 256 + tid;
    int d = (i < NN) ? g_deg[i] : 0;
    s[tid] = d;
    __syncthreads();
    for (int off = 1; off < 256; off <<= 1) {
        int t = (tid >= off) ? s[tid - off] : 0;
        __syncthreads();
        s[tid] += t;
        __syncthreads();
    }
    if (i < NN) {
        int e = base + s[tid] - d;
        g_rowptr[i] = e;
        g_cursor[i] = e;
    }
    if (bid == NBLK - 1 && tid == 255) g_rowptr[NN] = base + s[255];
}

__global__ void k_scatter(const int* __restrict__ src) {
    int i = blockIdx.x * blockDim.x + threadIdx.x;
    if (i < EE) {
        int p = atomicAdd(&g_cursor[src[i]], 1);
        g_eids[p] = i;
    }
}

// ---------------- pass1: EDGE-ordered, 8 lanes/edge, 4 EDGES PER THREAD -----
// Streaming u-loop: per 32-float row chunk u, load t/q for 4 edges then reuse
// each emb LDS for 4 dots. L1 ops/edge: 8 LDG + 4 LDS (was 24 in R12).
// Bounds: EE not divisible by 128 -> last warp predicated per edge.
__global__ void __launch_bounds__(256)
k_pass1(const float* __restrict__ tf, const int* __restrict__ src,
        const float* __restrict__ cemb) {
    __shared__ float4 emb_s[CC * 32];
    __shared__ int s_f[CC];
    if (threadIdx.x < CC) s_f[threadIdx.x] = 0;
    for (int i = threadIdx.x; i < CC * 32; i += blockDim.x)
        emb_s[i] = ((const float4*)cemb)[i];
    __syncthreads();

    int gw = (blockIdx.x * blockDim.x + threadIdx.x) >> 5;
    int lane = threadIdx.x & 31;
    int sub = lane >> 3;
    int l = lane & 7;
    int e0 = gw * 16 + sub;        // edges e0, e0+4, e0+8, e0+12

    int eidx[4], sidx[4];
    bool valid[4];
#pragma unroll
    for (int j = 0; j < 4; j++) {
        int e = e0 + j * 4;
        valid[j] = e < EE;
        eidx[j] = valid[j] ? e : (EE - 1);          // clamp for safe loads
        sidx[j] = __ldg(&src[eidx[j]]);
    }

    float p[4][CC + 1];
#pragma unroll
    for (int j = 0; j < 4; j++)
#pragma unroll
        for (int v = 0; v <= CC; v++) p[j][v] = 0.f;

#pragma unroll
    for (int u = 0; u < 4; u++) {
        float4 t[4], q[4];
#pragma unroll
        for (int j = 0; j < 4; j++) {
            t[j] = __ldg(&((const float4*)tf)[(size_t)eidx[j] * 32 + u * 8 + l]);
            q[j] = __ldg(&((const float4*)g_qp)[(size_t)sidx[j] * 32 + u * 8 + l]);
        }
#pragma unroll
        for (int c = 0; c < CC; c++) {
            float4 ev = emb_s[c * 32 + u * 8 + l];   // one LDS, four dots
#pragma unroll
            for (int j = 0; j < 4; j++) p[j][c] += dot4(t[j], ev);
        }
#pragma unroll
        for (int j = 0; j < 4; j++) p[j][CC] += dot4(t[j], q[j]);
    }

#pragma unroll
    for (int j = 0; j < 4; j++)
#pragma unroll
        for (int v = 0; v <= CC; v++)
#pragma unroll
            for (int off = 4; off; off >>= 1)
                p[j][v] += __shfl_xor_sync(0xffffffffu, p[j][v], off);

    if (l == 0) {
#pragma unroll
        for (int j = 0; j < 4; j++) {
            if (!valid[j]) continue;
            int best = 0; float bvv = p[j][0];
#pragma unroll
            for (int c = 1; c < CC; c++) if (p[j][c] > bvv) { bvv = p[j][c]; best = c; }
            g_ex[eidx[j]] = __expf((p[j][CC] + __ldg(&g_qb[sidx[j]])) * SCALEF);
            g_as[eidx[j]] = best;
            s_f[best] = 1;
        }
    }
    __syncthreads();
    if (threadIdx.x < CC && s_f[threadIdx.x]) g_cflag[threadIdx.x] = 1;
}

// ---------------- pass2: WARP per node (R9 shape; ex/as gathered via eid) ---
#define P2_WPB 8
__global__ void __launch_bounds__(32 * P2_WPB) k_pass2(const float* __restrict__ tf) {
    __shared__ float s_den[P2_WPB][CC];
    __shared__ int   s_cnt[P2_WPB][CC];

    int warp = threadIdx.x >> 5;
    int lane = threadIdx.x & 31;
    int n = blockIdx.x * P2_WPB + warp;
    if (n >= NN) return;

    if (lane < CC) { s_den[warp][lane] = 0.f; s_cnt[warp][lane] = 0; }
    __syncwarp();

    int beg = __ldg(&g_rowptr[n]);
    int deg = __ldg(&g_rowptr[n + 1]) - beg;
    int rounds = (deg + 31) >> 5;

    float4 acc = make_float4(0.f, 0.f, 0.f, 0.f);
    float sSum = 0.f;

    for (int r0 = 0; r0 < rounds; r0++) {
        int k = r0 * 32 + lane;
        bool on = k < deg;
        float ex = 0.f; int a = 0, eid = 0;
        if (on) {
            eid = __ldg(&g_eids[beg + k]);
            ex  = __ldg(&g_ex[eid]);
            a   = __ldg(&g_as[eid]);
            atomicAdd(&s_den[warp][a], ex);
            atomicAdd(&s_cnt[warp][a], 1);
        }
        __syncwarp();
        float cf = 0.f;
        if (on) cf = ex / (s_den[warp][a] * (float)s_cnt[warp][a]);
        if (rounds == 1) {
            sSum += cf;
            int cnt = deg;
#pragma unroll 4
            for (int kk = 0; kk < 32; kk++) {
                if (kk >= cnt) break;
                float c  = __shfl_sync(0xffffffffu, cf, kk);
                int   ee = __shfl_sync(0xffffffffu, eid, kk);
                float4 tv = __ldg(&((const float4*)tf)[(size_t)ee * 32 + lane]);
                acc.x += c * tv.x; acc.y += c * tv.y;
                acc.z += c * tv.z; acc.w += c * tv.w;
            }
        }
    }

    if (rounds > 1) {
        __syncwarp();
        for (int r0 = 0; r0 < rounds; r0++) {
            int k = r0 * 32 + lane;
            bool on = k < deg;
            float cf = 0.f; int eid = 0;
            if (on) {
                eid = __ldg(&g_eids[beg + k]);
                float ex = __ldg(&g_ex[eid]);
                int a = __ldg(&g_as[eid]);
                cf = ex / (s_den[warp][a] * (float)s_cnt[warp][a]);
            }
            sSum += cf;
            int cnt = deg - r0 * 32; if (cnt > 32) cnt = 32;
            for (int kk = 0; kk < cnt; kk++) {
                float c  = __shfl_sync(0xffffffffu, cf, kk);
                int   ee = __shfl_sync(0xffffffffu, eid, kk);
                float4 tv = __ldg(&((const float4*)tf)[(size_t)ee * 32 + lane]);
                acc.x += c * tv.x; acc.y += c * tv.y;
                acc.z += c * tv.z; acc.w += c * tv.w;
            }
        }
    }

    ((float4*)g_U)[(size_t)n * 32 + lane] = acc;

#pragma unroll
    for (int off = 16; off; off >>= 1) sSum += __shfl_xor_sync(0xffffffffu, sSum, off);
    if (lane == 0) g_S[n] = sSum;
}

// ---------------- final GEMM: out = relu(invnn*(U@Wvo + S*bvo) + bo) --------
__global__ void __launch_bounds__(256, 2)
k_gemm_final(const float* __restrict__ A, const float* __restrict__ bo,
             float* __restrict__ out) {
    extern __shared__ float smem[];
    float4* Ws4 = (float4*)smem;
    float4* As4 = (float4*)(smem + DD * DD);
    const ulonglong2* WsU = (const ulonglong2*)smem;

    for (int i = threadIdx.x; i < DD * DD / 4; i += 256)
        Ws4[i] = ((const float4*)g_Wvo)[i];
    __syncthreads();

    int r = threadIdx.x >> 5;
    int jc = threadIdx.x & 31;

    int nn = 0;
#pragma unroll
    for (int c = 0; c < CC; c++) nn += g_cflag[c];
    if (nn < 1) nn = 1;
    float gs = 1.f / (float)nn;

    int row0 = blockIdx.x * 64;
    for (int i = threadIdx.x; i < 64 * 32; i += 256) {
        int rr = i >> 5, cc = i & 31;
        float4 v = make_float4(0.f, 0.f, 0.f, 0.f);
        if (row0 + rr < NN) v = ((const float4*)A)[(size_t)(row0 + rr) * 32 + cc];
        As4[i] = v;
    }
    __syncthreads();

    unsigned long long acc2[8][2];
#pragma unroll
    for (int a = 0; a < 8; a++) { acc2[a][0] = 0ull; acc2[a][1] = 0ull; }

#pragma unroll 2
    for (int k4 = 0; k4 < 32; k4++) {
        float4 a4[8];
#pragma unroll
        for (int rr = 0; rr < 8; rr++) a4[rr] = As4[(r * 8 + rr) * 32 + k4];
#pragma unroll
        for (int kk = 0; kk < 4; kk++) {
            int k = k4 * 4 + kk;
            ulonglong2 w = WsU[k * 32 + jc];
#pragma unroll
            for (int rr = 0; rr < 8; rr++) {
                float av = (kk == 0) ? a4[rr].x : (kk == 1) ? a4[rr].y
                         : (kk == 2) ? a4[rr].z : a4[rr].w;
                unsigned long long av2 = pack2(av);
                ffma2(acc2[rr][0], av2, w.x);
                ffma2(acc2[rr][1], av2, w.y);
            }
        }
    }

    float4 b0 = ((const float4*)bo)[jc];
    float4 v0 = ((const float4*)g_bvo)[jc];

#pragma unroll
    for (int rr = 0; rr < 8; rr++) {
        int row = row0 + r * 8 + rr;
        if (row < NN) {
            float sc = g_S[row];
            float o[4];
            unpack2(acc2[rr][0], o[0], o[1]);
            unpack2(acc2[rr][1], o[2], o[3]);
            o[0] = fmaxf(gs * (o[0] + sc * v0.x) + b0.x, 0.f);
            o[1] = fmaxf(gs * (o[1] + sc * v0.y) + b0.y, 0.f);
            o[2] = fmaxf(gs * (o[2] + sc * v0.z) + b0.z, 0.f);
            o[3] = fmaxf(gs * (o[3] + sc * v0.w) + b0.w, 0.f);
            ((float4*)out)[(size_t)row * 32 + jc] = make_float4(o[0], o[1], o[2], o[3]);
        }
    }
}

// ---------------- launch ----------------
extern "C" void kernel_launch(void* const* d_in, const int* in_sizes, int n_in,
                              void* d_out, int out_size) {
    const float* node_feat = (const float*)d_in[0];
    const float* time_feat = (const float*)d_in[1];
    const int*   edge_index = (const int*)d_in[3];
    const float* Wq = (const float*)d_in[4];
    const float* bq = (const float*)d_in[5];
    const float* Wk = (const float*)d_in[6];
    const float* bk = (const float*)d_in[7];
    const float* Wv = (const float*)d_in[8];
    const float* bv = (const float*)d_in[9];
    const float* cemb = (const float*)d_in[10];
    const float* Wo = (const float*)d_in[11];
    const float* bo = (const float*)d_in[12];
    const int* src = edge_index;           // row 0 of [2,E]
    float* out = (float*)d_out;

    void* pU;
    cudaGetSymbolAddress(&pU, g_U);

    const int smemGemm = (DD * DD + 64 * DD) * (int)sizeof(float);   // 96 KB
    cudaFuncSetAttribute(k_combo1,     cudaFuncAttributeMaxDynamicSharedMemorySize, smemGemm);
    cudaFuncSetAttribute(k_combo2,     cudaFuncAttributeMaxDynamicSharedMemorySize, smemGemm);
    cudaFuncSetAttribute(k_gemm_final, cudaFuncAttributeMaxDynamicSharedMemorySize, smemGemm);

    const int zb = (NN + 127) / 128;
    k_prep<<<DD + 1 + zb, 128>>>(Wq, bq, Wk, bk, bv, Wo);                        // 1
    k_combo1<<<4 + (EE + 255) / 256, 256, smemGemm>>>(Wq, Wv, Wo, src);          // 2
    k_combo2<<<QPTILES + NBLK, 256, smemGemm>>>(node_feat);                      // 3
    k_pass1<<<(EE + 127) / 128, 256>>>(time_feat, src, cemb);                    // 4 <- profiled
    k_scanC2<<<NBLK, 256>>>();                                                   // 5
    k_scatter<<<(EE + 255) / 256, 256>>>(src);                                   // 6
    k_pass2<<<(NN + P2_WPB - 1) / P2_WPB, 32 * P2_WPB>>>(time_feat);             // 7
    k_gemm_final<<<(NN + 63) / 64, 256, smemGemm>>>((const float*)pU, bo, out);  // 8
}

// round 16
// speedup vs baseline: 1.1238x; 1.1238x over previous
#include <cuda_runtime.h>
#include <math.h>

#define NN 50000
#define EE 600000
#define DD 128
#define CC 8
#define SCALEF 0.08838834764831845f   // 128^-0.5
#define NBLK 196                       // scan blocks: ceil(50000/256)
#define QPTILES 782                    // ceil(50000/64)

// ---------------- static device scratch ----------------
__device__ __align__(16) int   g_deg[NN];
__device__ __align__(16) int   g_rowptr[NN + 1];
__device__ __align__(16) int   g_cursor[NN];
__device__ __align__(16) int   g_eids[EE];
__device__ __align__(16) int   g_bsum[NBLK];
__device__ __align__(16) float g_WkT[DD * DD];
__device__ __align__(16) float g_Wqk[DD * DD];
__device__ __align__(16) float g_Wvo[DD * DD];
__device__ __align__(16) float g_bqk[DD];
__device__ __align__(16) float g_bvo[DD];
__device__ __align__(16) float g_wqbk[DD];
__device__            float g_bqbk;
__device__ __align__(16) float g_qp[(size_t)NN * DD];
__device__ __align__(16) float g_qb[NN];
__device__ __align__(16) float g_ex[EE];     // exp(attn), EDGE order
__device__ __align__(16) int   g_as[EE];     // cluster assign, EDGE order
__device__ __align__(16) int   g_cflag[CC];
__device__ __align__(16) float g_U[(size_t)NN * DD];
__device__ __align__(16) float g_S[NN];

// ---------------- packed f32x2 helpers ----------------
__device__ __forceinline__ unsigned long long pack2(float x) {
    unsigned long long r;
    unsigned u = __float_as_uint(x);
    asm("mov.b64 %0, {%1, %1};" : "=l"(r) : "r"(u));
    return r;
}
__device__ __forceinline__ void ffma2(unsigned long long& d, unsigned long long a,
                                      unsigned long long b) {
    asm("fma.rn.f32x2 %0, %1, %2, %0;" : "+l"(d) : "l"(a), "l"(b));
}
__device__ __forceinline__ void unpack2(unsigned long long v, float& lo, float& hi) {
    unsigned a, b;
    asm("mov.b64 {%0, %1}, %2;" : "=r"(a), "=r"(b) : "l"(v));
    lo = __uint_as_float(a); hi = __uint_as_float(b);
}
__device__ __forceinline__ float dot4(float4 a, float4 b) {
    return a.x * b.x + a.y * b.y + a.z * b.z + a.w * b.w;
}

// ---------------- prep + init fused ----------------
__global__ void k_prep(const float* __restrict__ Wq, const float* __restrict__ bq,
                       const float* __restrict__ Wk, const float* __restrict__ bk,
                       const float* __restrict__ bv, const float* __restrict__ Wo) {
    int b = blockIdx.x;
    if (b < DD) {
        int r = b, c = threadIdx.x;
        g_WkT[c * DD + r] = Wk[r * DD + c];
    } else if (b == DD) {
        int j = threadIdx.x;
        float s1 = 0.f, s2 = 0.f, s3 = 0.f;
        for (int l = 0; l < DD; l++) {
            s1 += bq[l] * Wk[j * DD + l];      // bqk  = bq @ Wk^T
            s2 += bv[l] * Wo[l * DD + j];      // bvo  = bv @ Wo
            s3 += Wq[j * DD + l] * bk[l];      // wqbk = Wq @ bk
        }
        g_bqk[j] = s1; g_bvo[j] = s2; g_wqbk[j] = s3;
        if (j < CC) g_cflag[j] = 0;
        if (j == 0) {
            float t = 0.f;
            for (int l = 0; l < DD; l++) t += bq[l] * bk[l];
            g_bqbk = t;
        }
    } else {
        int i = (b - DD - 1) * blockDim.x + threadIdx.x;
        if (i < NN) g_deg[i] = 0;
    }
}

// ---------------- shared GEMM tile helpers (64 rows x 128 cols, 256 thr) ----
__device__ __forceinline__ void dgemm_weight(const float* __restrict__ A,
                                             const float* __restrict__ W,
                                             float* __restrict__ out, int tile) {
    extern __shared__ float smem[];
    float4* Ws4 = (float4*)smem;
    float4* As4 = (float4*)(smem + DD * DD);
    const ulonglong2* WsU = (const ulonglong2*)smem;

    for (int i = threadIdx.x; i < DD * DD / 4; i += 256)
        Ws4[i] = ((const float4*)W)[i];
    int row0 = tile * 64;
    for (int i = threadIdx.x; i < 64 * 32; i += 256) {
        int rr = i >> 5, cc = i & 31;
        As4[i] = ((const float4*)A)[(size_t)(row0 + rr) * 32 + cc];
    }
    __syncthreads();

    int r = threadIdx.x >> 5;
    int jc = threadIdx.x & 31;

    unsigned long long acc2[8][2];
#pragma unroll
    for (int a = 0; a < 8; a++) { acc2[a][0] = 0ull; acc2[a][1] = 0ull; }

#pragma unroll 2
    for (int k4 = 0; k4 < 32; k4++) {
        float4 a4[8];
#pragma unroll
        for (int rr = 0; rr < 8; rr++) a4[rr] = As4[(r * 8 + rr) * 32 + k4];
#pragma unroll
        for (int kk = 0; kk < 4; kk++) {
            int k = k4 * 4 + kk;
            ulonglong2 w = WsU[k * 32 + jc];
#pragma unroll
            for (int rr = 0; rr < 8; rr++) {
                float av = (kk == 0) ? a4[rr].x : (kk == 1) ? a4[rr].y
                         : (kk == 2) ? a4[rr].z : a4[rr].w;
                unsigned long long av2 = pack2(av);
                ffma2(acc2[rr][0], av2, w.x);
                ffma2(acc2[rr][1], av2, w.y);
            }
        }
    }
#pragma unroll
    for (int rr = 0; rr < 8; rr++) {
        int row = row0 + r * 8 + rr;
        float o[4];
        unpack2(acc2[rr][0], o[0], o[1]);
        unpack2(acc2[rr][1], o[2], o[3]);
        ((float4*)out)[(size_t)row * 32 + jc] = make_float4(o[0], o[1], o[2], o[3]);
    }
}

__device__ __forceinline__ void dgemm_qp(const float* __restrict__ A, int tile) {
    extern __shared__ float smem[];
    float4* Ws4 = (float4*)smem;
    float4* As4 = (float4*)(smem + DD * DD);
    const ulonglong2* WsU = (const ulonglong2*)smem;

    for (int i = threadIdx.x; i < DD * DD / 4; i += 256)
        Ws4[i] = ((const float4*)g_Wqk)[i];
    int row0 = tile * 64;
    for (int i = threadIdx.x; i < 64 * 32; i += 256) {
        int rr = i >> 5, cc = i & 31;
        float4 v = make_float4(0.f, 0.f, 0.f, 0.f);
        if (row0 + rr < NN) v = ((const float4*)A)[(size_t)(row0 + rr) * 32 + cc];
        As4[i] = v;
    }
    __syncthreads();

    int r = threadIdx.x >> 5;
    int jc = threadIdx.x & 31;

    unsigned long long acc2[8][2];
#pragma unroll
    for (int a = 0; a < 8; a++) { acc2[a][0] = 0ull; acc2[a][1] = 0ull; }

#pragma unroll 2
    for (int k4 = 0; k4 < 32; k4++) {
        float4 a4[8];
#pragma unroll
        for (int rr = 0; rr < 8; rr++) a4[rr] = As4[(r * 8 + rr) * 32 + k4];
#pragma unroll
        for (int kk = 0; kk < 4; kk++) {
            int k = k4 * 4 + kk;
            ulonglong2 w = WsU[k * 32 + jc];
#pragma unroll
            for (int rr = 0; rr < 8; rr++) {
                float av = (kk == 0) ? a4[rr].x : (kk == 1) ? a4[rr].y
                         : (kk == 2) ? a4[rr].z : a4[rr].w;
                unsigned long long av2 = pack2(av);
                ffma2(acc2[rr][0], av2, w.x);
                ffma2(acc2[rr][1], av2, w.y);
            }
        }
    }

    // fused qb epilogue
    {
        float4 wq = ((const float4*)g_wqbk)[jc];
#pragma unroll
        for (int rr = 0; rr < 8; rr++) {
            int row = row0 + r * 8 + rr;
            float4 a0 = As4[(r * 8 + rr) * 32 + jc];
            float part = dot4(a0, wq);
#pragma unroll
            for (int off = 16; off; off >>= 1)
                part += __shfl_xor_sync(0xffffffffu, part, off);
            if (jc == 0 && row < NN) g_qb[row] = part + g_bqbk;
        }
    }

    float4 b0 = ((const float4*)g_bqk)[jc];
#pragma unroll
    for (int rr = 0; rr < 8; rr++) {
        int row = row0 + r * 8 + rr;
        if (row < NN) {
            float o[4];
            unpack2(acc2[rr][0], o[0], o[1]);
            unpack2(acc2[rr][1], o[2], o[3]);
            o[0] += b0.x; o[1] += b0.y; o[2] += b0.z; o[3] += b0.w;
            ((float4*)g_qp)[(size_t)row * 32 + jc] = make_float4(o[0], o[1], o[2], o[3]);
        }
    }
}

// ---------------- combo1: weight GEMMs + histogram ----------------
__global__ void __launch_bounds__(256, 2)
k_combo1(const float* __restrict__ Wq, const float* __restrict__ Wv,
         const float* __restrict__ Wo, const int* __restrict__ src) {
    if (blockIdx.x < 2) {
        dgemm_weight(Wq, g_WkT, g_Wqk, blockIdx.x);
    } else if (blockIdx.x < 4) {
        dgemm_weight(Wv, Wo, g_Wvo, blockIdx.x - 2);
    } else {
        int i = (blockIdx.x - 4) * 256 + threadIdx.x;
        if (i < EE) atomicAdd(&g_deg[src[i]], 1);
    }
}

// ---------------- combo2: qp GEMM + scanA ----------------
__global__ void __launch_bounds__(256, 2)
k_combo2(const float* __restrict__ nf) {
    if (blockIdx.x < QPTILES) {
        dgemm_qp(nf, blockIdx.x);
    } else {
        __shared__ int red[256];
        int sb = blockIdx.x - QPTILES;
        int i = sb * 256 + threadIdx.x;
        int v = (i < NN) ? g_deg[i] : 0;
        red[threadIdx.x] = v;
        __syncthreads();
        for (int off = 128; off; off >>= 1) {
            if (threadIdx.x < off) red[threadIdx.x] += red[threadIdx.x + off];
            __syncthreads();
        }
        if (threadIdx.x == 0) g_bsum[sb] = red[0];
    }
}

// ---------------- scanC2: per-block offset from bsum + local scan ----------
__global__ void k_scanC2() {
    __shared__ int s[256];
    __shared__ int s2[256];
    int tid = threadIdx.x, bid = blockIdx.x;
    int v = (tid < bid) ? g_bsum[tid] : 0;
    s2[tid] = v;
    __syncthreads();
    for (int off = 128; off; off >>= 1) {
        if (tid < off) s2[tid] += s2[tid + off];
        __syncthreads();
    }
    int base = s2[0];

    int i = bid * 256 + tid;
    int d = (i < NN) ? g_deg[i] : 0;
    s[tid] = d;
    __syncthreads();
    for (int off = 1; off < 256; off <<= 1) {
        int t = (tid >= off) ? s[tid - off] : 0;
        __syncthreads();
        s[tid] += t;
        __syncthreads();
    }
    if (i < NN) {
        int e = base + s[tid] - d;
        g_rowptr[i] = e;
        g_cursor[i] = e;
    }
    if (bid == NBLK - 1 && tid == 255) g_rowptr[NN] = base + s[255];
}

__global__ void k_scatter(const int* __restrict__ src) {
    int i = blockIdx.x * blockDim.x + threadIdx.x;
    if (i < EE) {
        int p = atomicAdd(&g_cursor[src[i]], 1);
        g_eids[p] = i;
    }
}

// ---------------- pass1: EDGE-ordered, 8 lanes/edge, 2 edges/thread ---------
// R13 shape (measured 103us) but with a STREAMING u-loop: t/q for each
// 32-float chunk are loaded inside the loop, cutting live registers from
// ~80 to ~50 so occupancy rises from 3 to 4-5 blocks/SM. L1 ops/edge
// unchanged (8 LDG + 8 LDS); achieved DRAM BW should rise with occupancy.
__global__ void __launch_bounds__(256)
k_pass1(const float* __restrict__ tf, const int* __restrict__ src,
        const float* __restrict__ cemb) {
    __shared__ float4 emb_s[CC * 32];
    __shared__ int s_f[CC];
    if (threadIdx.x < CC) s_f[threadIdx.x] = 0;
    for (int i = threadIdx.x; i < CC * 32; i += blockDim.x)
        emb_s[i] = ((const float4*)cemb)[i];
    __syncthreads();

    int gw = (blockIdx.x * blockDim.x + threadIdx.x) >> 5;
    int lane = threadIdx.x & 31;
    int sub = lane >> 3;
    int l = lane & 7;
    int e0 = gw * 8 + sub;         // grid exact: EE % 8 == 0, EE/64 blocks ok
    int e1 = e0 + 4;
    int s0 = __ldg(&src[e0]);
    int s1 = __ldg(&src[e1]);

    float p0[CC + 1], p1[CC + 1];
#pragma unroll
    for (int v = 0; v <= CC; v++) { p0[v] = 0.f; p1[v] = 0.f; }

#pragma unroll
    for (int u = 0; u < 4; u++) {
        float4 t0 = __ldg(&((const float4*)tf)[(size_t)e0 * 32 + u * 8 + l]);
        float4 t1 = __ldg(&((const float4*)tf)[(size_t)e1 * 32 + u * 8 + l]);
        float4 q0 = __ldg(&((const float4*)g_qp)[(size_t)s0 * 32 + u * 8 + l]);
        float4 q1 = __ldg(&((const float4*)g_qp)[(size_t)s1 * 32 + u * 8 + l]);
#pragma unroll
        for (int c = 0; c < CC; c++) {
            float4 ev = emb_s[c * 32 + u * 8 + l];   // one LDS, two dots
            p0[c] += dot4(t0, ev);
            p1[c] += dot4(t1, ev);
        }
        p0[CC] += dot4(t0, q0);
        p1[CC] += dot4(t1, q1);
    }

#pragma unroll
    for (int v = 0; v <= CC; v++) {
#pragma unroll
        for (int off = 4; off; off >>= 1) {
            p0[v] += __shfl_xor_sync(0xffffffffu, p0[v], off);
            p1[v] += __shfl_xor_sync(0xffffffffu, p1[v], off);
        }
    }

    if (l == 0) {
        int b0 = 0, b1 = 0; float m0 = p0[0], m1 = p1[0];
#pragma unroll
        for (int c = 1; c < CC; c++) {
            if (p0[c] > m0) { m0 = p0[c]; b0 = c; }
            if (p1[c] > m1) { m1 = p1[c]; b1 = c; }
        }
        g_ex[e0] = __expf((p0[CC] + __ldg(&g_qb[s0])) * SCALEF);
        g_ex[e1] = __expf((p1[CC] + __ldg(&g_qb[s1])) * SCALEF);
        g_as[e0] = b0;
        g_as[e1] = b1;
        s_f[b0] = 1;
        s_f[b1] = 1;
    }
    __syncthreads();
    if (threadIdx.x < CC && s_f[threadIdx.x]) g_cflag[threadIdx.x] = 1;
}

// ---------------- pass2: WARP per node (R9 shape; ex/as gathered via eid) ---
#define P2_WPB 8
__global__ void __launch_bounds__(32 * P2_WPB) k_pass2(const float* __restrict__ tf) {
    __shared__ float s_den[P2_WPB][CC];
    __shared__ int   s_cnt[P2_WPB][CC];

    int warp = threadIdx.x >> 5;
    int lane = threadIdx.x & 31;
    int n = blockIdx.x * P2_WPB + warp;
    if (n >= NN) return;

    if (lane < CC) { s_den[warp][lane] = 0.f; s_cnt[warp][lane] = 0; }
    __syncwarp();

    int beg = __ldg(&g_rowptr[n]);
    int deg = __ldg(&g_rowptr[n + 1]) - beg;
    int rounds = (deg + 31) >> 5;

    float4 acc = make_float4(0.f, 0.f, 0.f, 0.f);
    float sSum = 0.f;

    for (int r0 = 0; r0 < rounds; r0++) {
        int k = r0 * 32 + lane;
        bool on = k < deg;
        float ex = 0.f; int a = 0, eid = 0;
        if (on) {
            eid = __ldg(&g_eids[beg + k]);
            ex  = __ldg(&g_ex[eid]);
            a   = __ldg(&g_as[eid]);
            atomicAdd(&s_den[warp][a], ex);
            atomicAdd(&s_cnt[warp][a], 1);
        }
        __syncwarp();
        float cf = 0.f;
        if (on) cf = ex / (s_den[warp][a] * (float)s_cnt[warp][a]);
        if (rounds == 1) {
            sSum += cf;
            int cnt = deg;
#pragma unroll 4
            for (int kk = 0; kk < 32; kk++) {
                if (kk >= cnt) break;
                float c  = __shfl_sync(0xffffffffu, cf, kk);
                int   ee = __shfl_sync(0xffffffffu, eid, kk);
                float4 tv = __ldg(&((const float4*)tf)[(size_t)ee * 32 + lane]);
                acc.x += c * tv.x; acc.y += c * tv.y;
                acc.z += c * tv.z; acc.w += c * tv.w;
            }
        }
    }

    if (rounds > 1) {
        __syncwarp();
        for (int r0 = 0; r0 < rounds; r0++) {
            int k = r0 * 32 + lane;
            bool on = k < deg;
            float cf = 0.f; int eid = 0;
            if (on) {
                eid = __ldg(&g_eids[beg + k]);
                float ex = __ldg(&g_ex[eid]);
                int a = __ldg(&g_as[eid]);
                cf = ex / (s_den[warp][a] * (float)s_cnt[warp][a]);
            }
            sSum += cf;
            int cnt = deg - r0 * 32; if (cnt > 32) cnt = 32;
            for (int kk = 0; kk < cnt; kk++) {
                float c  = __shfl_sync(0xffffffffu, cf, kk);
                int   ee = __shfl_sync(0xffffffffu, eid, kk);
                float4 tv = __ldg(&((const float4*)tf)[(size_t)ee * 32 + lane]);
                acc.x += c * tv.x; acc.y += c * tv.y;
                acc.z += c * tv.z; acc.w += c * tv.w;
            }
        }
    }

    ((float4*)g_U)[(size_t)n * 32 + lane] = acc;

#pragma unroll
    for (int off = 16; off; off >>= 1) sSum += __shfl_xor_sync(0xffffffffu, sSum, off);
    if (lane == 0) g_S[n] = sSum;
}

// ---------------- final GEMM: out = relu(invnn*(U@Wvo + S*bvo) + bo) --------
__global__ void __launch_bounds__(256, 2)
k_gemm_final(const float* __restrict__ A, const float* __restrict__ bo,
             float* __restrict__ out) {
    extern __shared__ float smem[];
    float4* Ws4 = (float4*)smem;
    float4* As4 = (float4*)(smem + DD * DD);
    const ulonglong2* WsU = (const ulonglong2*)smem;

    for (int i = threadIdx.x; i < DD * DD / 4; i += 256)
        Ws4[i] = ((const float4*)g_Wvo)[i];
    __syncthreads();

    int r = threadIdx.x >> 5;
    int jc = threadIdx.x & 31;

    int nn = 0;
#pragma unroll
    for (int c = 0; c < CC; c++) nn += g_cflag[c];
    if (nn < 1) nn = 1;
    float gs = 1.f / (float)nn;

    int row0 = blockIdx.x * 64;
    for (int i = threadIdx.x; i < 64 * 32; i += 256) {
        int rr = i >> 5, cc = i & 31;
        float4 v = make_float4(0.f, 0.f, 0.f, 0.f);
        if (row0 + rr < NN) v = ((const float4*)A)[(size_t)(row0 + rr) * 32 + cc];
        As4[i] = v;
    }
    __syncthreads();

    unsigned long long acc2[8][2];
#pragma unroll
    for (int a = 0; a < 8; a++) { acc2[a][0] = 0ull; acc2[a][1] = 0ull; }

#pragma unroll 2
    for (int k4 = 0; k4 < 32; k4++) {
        float4 a4[8];
#pragma unroll
        for (int rr = 0; rr < 8; rr++) a4[rr] = As4[(r * 8 + rr) * 32 + k4];
#pragma unroll
        for (int kk = 0; kk < 4; kk++) {
            int k = k4 * 4 + kk;
            ulonglong2 w = WsU[k * 32 + jc];
#pragma unroll
            for (int rr = 0; rr < 8; rr++) {
                float av = (kk == 0) ? a4[rr].x : (kk == 1) ? a4[rr].y
                         : (kk == 2) ? a4[rr].z : a4[rr].w;
                unsigned long long av2 = pack2(av);
                ffma2(acc2[rr][0], av2, w.x);
                ffma2(acc2[rr][1], av2, w.y);
            }
        }
    }

    float4 b0 = ((const float4*)bo)[jc];
    float4 v0 = ((const float4*)g_bvo)[jc];

#pragma unroll
    for (int rr = 0; rr < 8; rr++) {
        int row = row0 + r * 8 + rr;
        if (row < NN) {
            float sc = g_S[row];
            float o[4];
            unpack2(acc2[rr][0], o[0], o[1]);
            unpack2(acc2[rr][1], o[2], o[3]);
            o[0] = fmaxf(gs * (o[0] + sc * v0.x) + b0.x, 0.f);
            o[1] = fmaxf(gs * (o[1] + sc * v0.y) + b0.y, 0.f);
            o[2] = fmaxf(gs * (o[2] + sc * v0.z) + b0.z, 0.f);
            o[3] = fmaxf(gs * (o[3] + sc * v0.w) + b0.w, 0.f);
            ((float4*)out)[(size_t)row * 32 + jc] = make_float4(o[0], o[1], o[2], o[3]);
        }
    }
}

// ---------------- launch ----------------
extern "C" void kernel_launch(void* const* d_in, const int* in_sizes, int n_in,
                              void* d_out, int out_size) {
    const float* node_feat = (const float*)d_in[0];
    const float* time_feat = (const float*)d_in[1];
    const int*   edge_index = (const int*)d_in[3];
    const float* Wq = (const float*)d_in[4];
    const float* bq = (const float*)d_in[5];
    const float* Wk = (const float*)d_in[6];
    const float* bk = (const float*)d_in[7];
    const float* Wv = (const float*)d_in[8];
    const float* bv = (const float*)d_in[9];
    const float* cemb = (const float*)d_in[10];
    const float* Wo = (const float*)d_in[11];
    const float* bo = (const float*)d_in[12];
    const int* src = edge_index;           // row 0 of [2,E]
    float* out = (float*)d_out;

    void* pU;
    cudaGetSymbolAddress(&pU, g_U);

    const int smemGemm = (DD * DD + 64 * DD) * (int)sizeof(float);   // 96 KB
    cudaFuncSetAttribute(k_combo1,     cudaFuncAttributeMaxDynamicSharedMemorySize, smemGemm);
    cudaFuncSetAttribute(k_combo2,     cudaFuncAttributeMaxDynamicSharedMemorySize, smemGemm);
    cudaFuncSetAttribute(k_gemm_final, cudaFuncAttributeMaxDynamicSharedMemorySize, smemGemm);

    const int zb = (NN + 127) / 128;
    k_prep<<<DD + 1 + zb, 128>>>(Wq, bq, Wk, bk, bv, Wo);                        // 1
    k_combo1<<<4 + (EE + 255) / 256, 256, smemGemm>>>(Wq, Wv, Wo, src);          // 2
    k_combo2<<<QPTILES + NBLK, 256, smemGemm>>>(node_feat);                      // 3
    k_pass1<<<EE / 64, 256>>>(time_feat, src, cemb);                             // 4 <- profiled
    k_scanC2<<<NBLK, 256>>>();                                                   // 5
    k_scatter<<<(EE + 255) / 256, 256>>>(src);                                   // 6
    k_pass2<<<(NN + P2_WPB - 1) / P2_WPB, 32 * P2_WPB>>>(time_feat);             // 7
    k_gemm_final<<<(NN + 63) / 64, 256, smemGemm>>>((const float*)pU, bo, out);  // 8
}

// round 17
// speedup vs baseline: 1.1698x; 1.0409x over previous
#include <cuda_runtime.h>
#include <math.h>

#define NN 50000
#define EE 600000
#define DD 128
#define CC 8
#define SCALEF 0.08838834764831845f   // 128^-0.5
#define NBLK 196                       // scan blocks: ceil(50000/256)
#define QPTILES 782                    // ceil(50000/64)

// ---------------- static device scratch ----------------
__device__ __align__(16) int   g_deg[NN];
__device__ __align__(16) int   g_rowptr[NN + 1];
__device__ __align__(16) int   g_cursor[NN];
__device__ __align__(16) int   g_eids[EE];
__device__ __align__(16) int   g_bsum[NBLK];
__device__ __align__(16) float g_WkT[DD * DD];
__device__ __align__(16) float g_Wqk[DD * DD];
__device__ __align__(16) float g_Wvo[DD * DD];
__device__ __align__(16) float g_bqk[DD];
__device__ __align__(16) float g_bvo[DD];
__device__ __align__(16) float g_wqbk[DD];
__device__            float g_bqbk;
__device__ __align__(16) float g_qp[(size_t)NN * DD];
__device__ __align__(16) float g_qb[NN];
__device__ __align__(16) float g_ex[EE];     // exp(attn), EDGE order
__device__ __align__(16) int   g_as[EE];     // cluster assign, EDGE order
__device__ __align__(16) int   g_cflag[CC];
__device__ __align__(16) float g_U[(size_t)NN * DD];
__device__ __align__(16) float g_S[NN];

// ---------------- packed f32x2 helpers ----------------
__device__ __forceinline__ unsigned long long pack2(float x) {
    unsigned long long r;
    unsigned u = __float_as_uint(x);
    asm("mov.b64 %0, {%1, %1};" : "=l"(r) : "r"(u));
    return r;
}
__device__ __forceinline__ void ffma2(unsigned long long& d, unsigned long long a,
                                      unsigned long long b) {
    asm("fma.rn.f32x2 %0, %1, %2, %0;" : "+l"(d) : "l"(a), "l"(b));
}
__device__ __forceinline__ void unpack2(unsigned long long v, float& lo, float& hi) {
    unsigned a, b;
    asm("mov.b64 {%0, %1}, %2;" : "=r"(a), "=r"(b) : "l"(v));
    lo = __uint_as_float(a); hi = __uint_as_float(b);
}
__device__ __forceinline__ float dot4(float4 a, float4 b) {
    return a.x * b.x + a.y * b.y + a.z * b.z + a.w * b.w;
}

// ---------------- prep + init fused ----------------
__global__ void k_prep(const float* __restrict__ Wq, const float* __restrict__ bq,
                       const float* __restrict__ Wk, const float* __restrict__ bk,
                       const float* __restrict__ bv, const float* __restrict__ Wo) {
    int b = blockIdx.x;
    if (b < DD) {
        int r = b, c = threadIdx.x;
        g_WkT[c * DD + r] = Wk[r * DD + c];
    } else if (b == DD) {
        int j = threadIdx.x;
        float s1 = 0.f, s2 = 0.f, s3 = 0.f;
        for (int l = 0; l < DD; l++) {
            s1 += bq[l] * Wk[j * DD + l];      // bqk  = bq @ Wk^T
            s2 += bv[l] * Wo[l * DD + j];      // bvo  = bv @ Wo
            s3 += Wq[j * DD + l] * bk[l];      // wqbk = Wq @ bk
        }
        g_bqk[j] = s1; g_bvo[j] = s2; g_wqbk[j] = s3;
        if (j < CC) g_cflag[j] = 0;
        if (j == 0) {
            float t = 0.f;
            for (int l = 0; l < DD; l++) t += bq[l] * bk[l];
            g_bqbk = t;
        }
    } else {
        int i = (b - DD - 1) * blockDim.x + threadIdx.x;
        if (i < NN) g_deg[i] = 0;
    }
}

// ---------------- GEMM tile helpers: 512 threads, 64 rows x 128 cols -------
// Thread (r = tid>>5 in 0..15, jc = tid&31): 4 rows x 4 cols. 32 warps/SM.
__device__ __forceinline__ void dgemm_weight(const float* __restrict__ A,
                                             const float* __restrict__ W,
                                             float* __restrict__ out, int tile) {
    extern __shared__ float smem[];
    float4* Ws4 = (float4*)smem;                 // 64 KB
    float4* As4 = (float4*)(smem + DD * DD);     // 32 KB
    const ulonglong2* WsU = (const ulonglong2*)smem;

    for (int i = threadIdx.x; i < DD * DD / 4; i += 512)
        Ws4[i] = ((const float4*)W)[i];
    int row0 = tile * 64;
    for (int i = threadIdx.x; i < 64 * 32; i += 512) {
        int rr = i >> 5, cc = i & 31;
        As4[i] = ((const float4*)A)[(size_t)(row0 + rr) * 32 + cc];
    }
    __syncthreads();

    int r = threadIdx.x >> 5;    // 0..15 (4 rows each), uniform per warp
    int jc = threadIdx.x & 31;   // 0..31 (4 cols each)

    unsigned long long acc2[4][2];
#pragma unroll
    for (int a = 0; a < 4; a++) { acc2[a][0] = 0ull; acc2[a][1] = 0ull; }

#pragma unroll 2
    for (int k4 = 0; k4 < 32; k4++) {
        float4 a4[4];
#pragma unroll
        for (int rr = 0; rr < 4; rr++) a4[rr] = As4[(r * 4 + rr) * 32 + k4];  // broadcast
#pragma unroll
        for (int kk = 0; kk < 4; kk++) {
            int k = k4 * 4 + kk;
            ulonglong2 w = WsU[k * 32 + jc];
#pragma unroll
            for (int rr = 0; rr < 4; rr++) {
                float av = (kk == 0) ? a4[rr].x : (kk == 1) ? a4[rr].y
                         : (kk == 2) ? a4[rr].z : a4[rr].w;
                unsigned long long av2 = pack2(av);
                ffma2(acc2[rr][0], av2, w.x);
                ffma2(acc2[rr][1], av2, w.y);
            }
        }
    }
#pragma unroll
    for (int rr = 0; rr < 4; rr++) {
        int row = row0 + r * 4 + rr;
        float o[4];
        unpack2(acc2[rr][0], o[0], o[1]);
        unpack2(acc2[rr][1], o[2], o[3]);
        ((float4*)out)[(size_t)row * 32 + jc] = make_float4(o[0], o[1], o[2], o[3]);
    }
}

__device__ __forceinline__ void dgemm_qp(const float* __restrict__ A, int tile) {
    extern __shared__ float smem[];
    float4* Ws4 = (float4*)smem;
    float4* As4 = (float4*)(smem + DD * DD);
    const ulonglong2* WsU = (const ulonglong2*)smem;

    for (int i = threadIdx.x; i < DD * DD / 4; i += 512)
        Ws4[i] = ((const float4*)g_Wqk)[i];
    int row0 = tile * 64;
    for (int i = threadIdx.x; i < 64 * 32; i += 512) {
        int rr = i >> 5, cc = i & 31;
        float4 v = make_float4(0.f, 0.f, 0.f, 0.f);
        if (row0 + rr < NN) v = ((const float4*)A)[(size_t)(row0 + rr) * 32 + cc];
        As4[i] = v;
    }
    __syncthreads();

    int r = threadIdx.x >> 5;
    int jc = threadIdx.x & 31;

    unsigned long long acc2[4][2];
#pragma unroll
    for (int a = 0; a < 4; a++) { acc2[a][0] = 0ull; acc2[a][1] = 0ull; }

#pragma unroll 2
    for (int k4 = 0; k4 < 32; k4++) {
        float4 a4[4];
#pragma unroll
        for (int rr = 0; rr < 4; rr++) a4[rr] = As4[(r * 4 + rr) * 32 + k4];
#pragma unroll
        for (int kk = 0; kk < 4; kk++) {
            int k = k4 * 4 + kk;
            ulonglong2 w = WsU[k * 32 + jc];
#pragma unroll
            for (int rr = 0; rr < 4; rr++) {
                float av = (kk == 0) ? a4[rr].x : (kk == 1) ? a4[rr].y
                         : (kk == 2) ? a4[rr].z : a4[rr].w;
                unsigned long long av2 = pack2(av);
                ffma2(acc2[rr][0], av2, w.x);
                ffma2(acc2[rr][1], av2, w.y);
            }
        }
    }

    // fused qb epilogue: per-row dot(A[row], wqbk), full-warp reduce
    {
        float4 wq = ((const float4*)g_wqbk)[jc];
#pragma unroll
        for (int rr = 0; rr < 4; rr++) {
            int row = row0 + r * 4 + rr;
            float4 a0 = As4[(r * 4 + rr) * 32 + jc];
            float part = dot4(a0, wq);
#pragma unroll
            for (int off = 16; off; off >>= 1)
                part += __shfl_xor_sync(0xffffffffu, part, off);
            if (jc == 0 && row < NN) g_qb[row] = part + g_bqbk;
        }
    }

    float4 b0 = ((const float4*)g_bqk)[jc];
#pragma unroll
    for (int rr = 0; rr < 4; rr++) {
        int row = row0 + r * 4 + rr;
        if (row < NN) {
            float o[4];
            unpack2(acc2[rr][0], o[0], o[1]);
            unpack2(acc2[rr][1], o[2], o[3]);
            o[0] += b0.x; o[1] += b0.y; o[2] += b0.z; o[3] += b0.w;
            ((float4*)g_qp)[(size_t)row * 32 + jc] = make_float4(o[0], o[1], o[2], o[3]);
        }
    }
}

// ---------------- combo1: weight GEMMs + histogram (512 threads) -----------
__global__ void __launch_bounds__(512, 2)
k_combo1(const float* __restrict__ Wq, const float* __restrict__ Wv,
         const float* __restrict__ Wo, const int* __restrict__ src) {
    if (blockIdx.x < 2) {
        dgemm_weight(Wq, g_WkT, g_Wqk, blockIdx.x);
    } else if (blockIdx.x < 4) {
        dgemm_weight(Wv, Wo, g_Wvo, blockIdx.x - 2);
    } else {
        int i = (blockIdx.x - 4) * 512 + threadIdx.x;
        if (i < EE) atomicAdd(&g_deg[src[i]], 1);
    }
}

// ---------------- combo2: qp GEMM + scanA (512 threads) --------------------
__global__ void __launch_bounds__(512, 2)
k_combo2(const float* __restrict__ nf) {
    if (blockIdx.x < QPTILES) {
        dgemm_qp(nf, blockIdx.x);
    } else {
        // scanA over 256-element chunks; all 512 threads join the reduction
        __shared__ int red[512];
        int sb = blockIdx.x - QPTILES;
        int tid = threadIdx.x;
        int v = 0;
        if (tid < 256) {
            int i = sb * 256 + tid;
            if (i < NN) v = g_deg[i];
        }
        red[tid] = v;
        __syncthreads();
        for (int off = 256; off; off >>= 1) {
            if (tid < off) red[tid] += red[tid + off];
            __syncthreads();
        }
        if (tid == 0) g_bsum[sb] = red[0];
    }
}

// ---------------- scanC2: per-block offset from bsum + local scan ----------
__global__ void k_scanC2() {
    __shared__ int s[256];
    __shared__ int s2[256];
    int tid = threadIdx.x, bid = blockIdx.x;
    int v = (tid < bid) ? g_bsum[tid] : 0;
    s2[tid] = v;
    __syncthreads();
    for (int off = 128; off; off >>= 1) {
        if (tid < off) s2[tid] += s2[tid + off];
        __syncthreads();
    }
    int base = s2[0];

    int i = bid * 256 + tid;
    int d = (i < NN) ? g_deg[i] : 0;
    s[tid] = d;
    __syncthreads();
    for (int off = 1; off < 256; off <<= 1) {
        int t = (tid >= off) ? s[tid - off] : 0;
        __syncthreads();
        s[tid] += t;
        __syncthreads();
    }
    if (i < NN) {
        int e = base + s[tid] - d;
        g_rowptr[i] = e;
        g_cursor[i] = e;
    }
    if (bid == NBLK - 1 && tid == 255) g_rowptr[NN] = base + s[255];
}

__global__ void k_scatter(const int* __restrict__ src) {
    int i = blockIdx.x * blockDim.x + threadIdx.x;
    if (i < EE) {
        int p = atomicAdd(&g_cursor[src[i]], 1);
        g_eids[p] = i;
    }
}

// ---------------- pass1: EDGE-ordered, 8 lanes/edge, 2 EDGES PER THREAD -----
// Exact R13 shape (measured 103.2us). Each emb float4 LDS serves 2 edges.
__global__ void __launch_bounds__(256, 3)
k_pass1(const float* __restrict__ tf, const int* __restrict__ src,
        const float* __restrict__ cemb) {
    __shared__ float4 emb_s[CC * 32];
    __shared__ int s_f[CC];
    if (threadIdx.x < CC) s_f[threadIdx.x] = 0;
    for (int i = threadIdx.x; i < CC * 32; i += blockDim.x)
        emb_s[i] = ((const float4*)cemb)[i];
    __syncthreads();

    int gw = (blockIdx.x * blockDim.x + threadIdx.x) >> 5;
    int lane = threadIdx.x & 31;
    int sub = lane >> 3;
    int l = lane & 7;
    int e0 = gw * 8 + sub;         // grid exact: EE % 64 == 0
    int e1 = e0 + 4;
    int s0 = __ldg(&src[e0]);
    int s1 = __ldg(&src[e1]);

    float4 t0[4], t1[4], q0[4], q1[4];
#pragma unroll
    for (int u = 0; u < 4; u++) {
        t0[u] = __ldg(&((const float4*)tf)[(size_t)e0 * 32 + u * 8 + l]);
        t1[u] = __ldg(&((const float4*)tf)[(size_t)e1 * 32 + u * 8 + l]);
        q0[u] = __ldg(&((const float4*)g_qp)[(size_t)s0 * 32 + u * 8 + l]);
        q1[u] = __ldg(&((const float4*)g_qp)[(size_t)s1 * 32 + u * 8 + l]);
    }

    float p0[CC + 1], p1[CC + 1];
#pragma unroll
    for (int c = 0; c < CC; c++) {
        float a0 = 0.f, a1 = 0.f;
#pragma unroll
        for (int u = 0; u < 4; u++) {
            float4 ev = emb_s[c * 32 + u * 8 + l];   // loaded once, used twice
            a0 += dot4(t0[u], ev);
            a1 += dot4(t1[u], ev);
        }
        p0[c] = a0; p1[c] = a1;
    }
    {
        float a0 = 0.f, a1 = 0.f;
#pragma unroll
        for (int u = 0; u < 4; u++) { a0 += dot4(t0[u], q0[u]); a1 += dot4(t1[u], q1[u]); }
        p0[CC] = a0; p1[CC] = a1;
    }

#pragma unroll
    for (int v = 0; v <= CC; v++) {
#pragma unroll
        for (int off = 4; off; off >>= 1) {
            p0[v] += __shfl_xor_sync(0xffffffffu, p0[v], off);
            p1[v] += __shfl_xor_sync(0xffffffffu, p1[v], off);
        }
    }

    if (l == 0) {
        int b0 = 0, b1 = 0; float m0 = p0[0], m1 = p1[0];
#pragma unroll
        for (int c = 1; c < CC; c++) {
            if (p0[c] > m0) { m0 = p0[c]; b0 = c; }
            if (p1[c] > m1) { m1 = p1[c]; b1 = c; }
        }
        g_ex[e0] = __expf((p0[CC] + __ldg(&g_qb[s0])) * SCALEF);
        g_ex[e1] = __expf((p1[CC] + __ldg(&g_qb[s1])) * SCALEF);
        g_as[e0] = b0;
        g_as[e1] = b1;
        s_f[b0] = 1;
        s_f[b1] = 1;
    }
    __syncthreads();
    if (threadIdx.x < CC && s_f[threadIdx.x]) g_cflag[threadIdx.x] = 1;
}

// ---------------- pass2: WARP per node (R9 shape; ex/as gathered via eid) ---
#define P2_WPB 8
__global__ void __launch_bounds__(32 * P2_WPB) k_pass2(const float* __restrict__ tf) {
    __shared__ float s_den[P2_WPB][CC];
    __shared__ int   s_cnt[P2_WPB][CC];

    int warp = threadIdx.x >> 5;
    int lane = threadIdx.x & 31;
    int n = blockIdx.x * P2_WPB + warp;
    if (n >= NN) return;

    if (lane < CC) { s_den[warp][lane] = 0.f; s_cnt[warp][lane] = 0; }
    __syncwarp();

    int beg = __ldg(&g_rowptr[n]);
    int deg = __ldg(&g_rowptr[n + 1]) - beg;
    int rounds = (deg + 31) >> 5;

    float4 acc = make_float4(0.f, 0.f, 0.f, 0.f);
    float sSum = 0.f;

    for (int r0 = 0; r0 < rounds; r0++) {
        int k = r0 * 32 + lane;
        bool on = k < deg;
        float ex = 0.f; int a = 0, eid = 0;
        if (on) {
            eid = __ldg(&g_eids[beg + k]);
            ex  = __ldg(&g_ex[eid]);
            a   = __ldg(&g_as[eid]);
            atomicAdd(&s_den[warp][a], ex);
            atomicAdd(&s_cnt[warp][a], 1);
        }
        __syncwarp();
        float cf = 0.f;
        if (on) cf = ex / (s_den[warp][a] * (float)s_cnt[warp][a]);
        if (rounds == 1) {
            sSum += cf;
            int cnt = deg;
#pragma unroll 4
            for (int kk = 0; kk < 32; kk++) {
                if (kk >= cnt) break;
                float c  = __shfl_sync(0xffffffffu, cf, kk);
                int   ee = __shfl_sync(0xffffffffu, eid, kk);
                float4 tv = __ldg(&((const float4*)tf)[(size_t)ee * 32 + lane]);
                acc.x += c * tv.x; acc.y += c * tv.y;
                acc.z += c * tv.z; acc.w += c * tv.w;
            }
        }
    }

    if (rounds > 1) {
        __syncwarp();
        for (int r0 = 0; r0 < rounds; r0++) {
            int k = r0 * 32 + lane;
            bool on = k < deg;
            float cf = 0.f; int eid = 0;
            if (on) {
                eid = __ldg(&g_eids[beg + k]);
                float ex = __ldg(&g_ex[eid]);
                int a = __ldg(&g_as[eid]);
                cf = ex / (s_den[warp][a] * (float)s_cnt[warp][a]);
            }
            sSum += cf;
            int cnt = deg - r0 * 32; if (cnt > 32) cnt = 32;
            for (int kk = 0; kk < cnt; kk++) {
                float c  = __shfl_sync(0xffffffffu, cf, kk);
                int   ee = __shfl_sync(0xffffffffu, eid, kk);
                float4 tv = __ldg(&((const float4*)tf)[(size_t)ee * 32 + lane]);
                acc.x += c * tv.x; acc.y += c * tv.y;
                acc.z += c * tv.z; acc.w += c * tv.w;
            }
        }
    }

    ((float4*)g_U)[(size_t)n * 32 + lane] = acc;

#pragma unroll
    for (int off = 16; off; off >>= 1) sSum += __shfl_xor_sync(0xffffffffu, sSum, off);
    if (lane == 0) g_S[n] = sSum;
}

// ---------------- final GEMM (512 threads): relu(gs*(U@Wvo+S*bvo)+bo) ------
__global__ void __launch_bounds__(512, 2)
k_gemm_final(const float* __restrict__ A, const float* __restrict__ bo,
             float* __restrict__ out) {
    extern __shared__ float smem[];
    float4* Ws4 = (float4*)smem;
    float4* As4 = (float4*)(smem + DD * DD);
    const ulonglong2* WsU = (const ulonglong2*)smem;

    for (int i = threadIdx.x; i < DD * DD / 4; i += 512)
        Ws4[i] = ((const float4*)g_Wvo)[i];
    __syncthreads();

    int r = threadIdx.x >> 5;
    int jc = threadIdx.x & 31;

    int nn = 0;
#pragma unroll
    for (int c = 0; c < CC; c++) nn += g_cflag[c];
    if (nn < 1) nn = 1;
    float gs = 1.f / (float)nn;

    int row0 = blockIdx.x * 64;
    for (int i = threadIdx.x; i < 64 * 32; i += 512) {
        int rr = i >> 5, cc = i & 31;
        float4 v = make_float4(0.f, 0.f, 0.f, 0.f);
        if (row0 + rr < NN) v = ((const float4*)A)[(size_t)(row0 + rr) * 32 + cc];
        As4[i] = v;
    }
    __syncthreads();

    unsigned long long acc2[4][2];
#pragma unroll
    for (int a = 0; a < 4; a++) { acc2[a][0] = 0ull; acc2[a][1] = 0ull; }

#pragma unroll 2
    for (int k4 = 0; k4 < 32; k4++) {
        float4 a4[4];
#pragma unroll
        for (int rr = 0; rr < 4; rr++) a4[rr] = As4[(r * 4 + rr) * 32 + k4];
#pragma unroll
        for (int kk = 0; kk < 4; kk++) {
            int k = k4 * 4 + kk;
            ulonglong2 w = WsU[k * 32 + jc];
#pragma unroll
            for (int rr = 0; rr < 4; rr++) {
                float av = (kk == 0) ? a4[rr].x : (kk == 1) ? a4[rr].y
                         : (kk == 2) ? a4[rr].z : a4[rr].w;
                unsigned long long av2 = pack2(av);
                ffma2(acc2[rr][0], av2, w.x);
                ffma2(acc2[rr][1], av2, w.y);
            }
        }
    }

    float4 b0 = ((const float4*)bo)[jc];
    float4 v0 = ((const float4*)g_bvo)[jc];

#pragma unroll
    for (int rr = 0; rr < 4; rr++) {
        int row = row0 + r * 4 + rr;
        if (row < NN) {
            float sc = g_S[row];
            float o[4];
            unpack2(acc2[rr][0], o[0], o[1]);
            unpack2(acc2[rr][1], o[2], o[3]);
            o[0] = fmaxf(gs * (o[0] + sc * v0.x) + b0.x, 0.f);
            o[1] = fmaxf(gs * (o[1] + sc * v0.y) + b0.y, 0.f);
            o[2] = fmaxf(gs * (o[2] + sc * v0.z) + b0.z, 0.f);
            o[3] = fmaxf(gs * (o[3] + sc * v0.w) + b0.w, 0.f);
            ((float4*)out)[(size_t)row * 32 + jc] = make_float4(o[0], o[1], o[2], o[3]);
        }
    }
}

// ---------------- launch ----------------
extern "C" void kernel_launch(void* const* d_in, const int* in_sizes, int n_in,
                              void* d_out, int out_size) {
    const float* node_feat = (const float*)d_in[0];
    const float* time_feat = (const float*)d_in[1];
    const int*   edge_index = (const int*)d_in[3];
    const float* Wq = (const float*)d_in[4];
    const float* bq = (const float*)d_in[5];
    const float* Wk = (const float*)d_in[6];
    const float* bk = (const float*)d_in[7];
    const float* Wv = (const float*)d_in[8];
    const float* bv = (const float*)d_in[9];
    const float* cemb = (const float*)d_in[10];
    const float* Wo = (const float*)d_in[11];
    const float* bo = (const float*)d_in[12];
    const int* src = edge_index;           // row 0 of [2,E]
    float* out = (float*)d_out;

    void* pU;
    cudaGetSymbolAddress(&pU, g_U);

    const int smemGemm = (DD * DD + 64 * DD) * (int)sizeof(float);   // 96 KB
    cudaFuncSetAttribute(k_combo1,     cudaFuncAttributeMaxDynamicSharedMemorySize, smemGemm);
    cudaFuncSetAttribute(k_combo2,     cudaFuncAttributeMaxDynamicSharedMemorySize, smemGemm);
    cudaFuncSetAttribute(k_gemm_final, cudaFuncAttributeMaxDynamicSharedMemorySize, smemGemm);

    const int zb = (NN + 127) / 128;
    k_prep<<<DD + 1 + zb, 128>>>(Wq, bq, Wk, bk, bv, Wo);                        // 1
    k_combo1<<<4 + (EE + 511) / 512, 512, smemGemm>>>(Wq, Wv, Wo, src);          // 2
    k_combo2<<<QPTILES + NBLK, 512, smemGemm>>>(node_feat);                      // 3
    k_pass1<<<EE / 64, 256>>>(time_feat, src, cemb);                             // 4 <- profiled
    k_scanC2<<<NBLK, 256>>>();                                                   // 5
    k_scatter<<<(EE + 255) / 256, 256>>>(src);                                   // 6
    k_pass2<<<(NN + P2_WPB - 1) / P2_WPB, 32 * P2_WPB>>>(time_feat);             // 7
    k_gemm_final<<<(NN + 63) / 64, 512, smemGemm>>>((const float*)pU, bo, out);  // 8
}